// round 15
// baseline (speedup 1.0000x reference)
#include <cuda_runtime.h>
#include <math.h>
#include <stdint.h>

#define NB   8192
#define LMAX 12
#define TT   10
#define EMB  300
#define EMBP 320      // padded to multiple of 32
#define CVEC 256
#define HID  256
#define OUTD 512
#define G4   1024     // 4*HID

#define BM 128
#define BN 128
#define BKT 32
#define SPAD 4
#define TILE_F (BKT + SPAD)
// dynamic smem: As[2][BM][TILE_F] + Bs[2][BN][TILE_F] = 73728 bytes
#define SMEM_BYTES (2 * (BM + BN) * TILE_F * 4)

// ---------------- scratch (static device globals; no allocations) ------------
__device__ __align__(128) float g_e   [TT * NB * EMBP];     // tf32-rounded, padded
__device__ __align__(128) float g_cv  [TT * NB * CVEC];     // tf32-rounded
__device__ __align__(128) float g_xg  [2][TT * NB * G4];    // fp32, gate-permuted n'=4*hid+gate
__device__ __align__(128) float g_hcat[TT * NB * 2 * HID];  // tf32-rounded; [t][b][dir*256+j]
__device__ __align__(128) float g_cs  [2][NB * HID];        // fp32 cell state
// pre-rounded / pre-permuted weights
__device__ __align__(128) float w_enc_t[CVEC * EMBP];
__device__ __align__(128) float w_ih_t [2][G4 * CVEC];
__device__ __align__(128) float w_hh_t [2][G4 * HID];
__device__ __align__(128) float w_out_t[OUTD * 2 * HID];
__device__ __align__(128) float bias_comb[2][G4];

// ---------------- helpers ----------------------------------------------------
__device__ __forceinline__ float f2tf32f(float x) {
    unsigned r;
    asm("cvt.rna.tf32.f32 %0, %1;" : "=r"(r) : "f"(x));
    return __uint_as_float(r);
}

__device__ __forceinline__ void mma_tf32(float* d, const unsigned* a, const unsigned* b) {
    asm volatile(
        "mma.sync.aligned.m16n8k8.row.col.f32.tf32.tf32.f32 "
        "{%0,%1,%2,%3}, {%4,%5,%6,%7}, {%8,%9}, {%0,%1,%2,%3};"
        : "+f"(d[0]), "+f"(d[1]), "+f"(d[2]), "+f"(d[3])
        : "r"(a[0]), "r"(a[1]), "r"(a[2]), "r"(a[3]), "r"(b[0]), "r"(b[1]));
}

__device__ __forceinline__ void cp16(void* smem_dst, const void* gsrc) {
    uint32_t d = (uint32_t)__cvta_generic_to_shared(smem_dst);
    asm volatile("cp.async.cg.shared.global [%0], [%1], 16;\n" :: "r"(d), "l"(gsrc));
}
__device__ __forceinline__ void cp_commit() { asm volatile("cp.async.commit_group;\n"); }
__device__ __forceinline__ void cp_wait1()  { asm volatile("cp.async.wait_group 1;\n"); }

// ---------------- prep kernels (tiny; run inside graph each call) -------------
__global__ void prep_enc(const float* __restrict__ w) {
    int n = blockIdx.x;
    for (int k = threadIdx.x; k < EMBP; k += blockDim.x)
        w_enc_t[n * EMBP + k] = (k < EMB) ? f2tf32f(w[n * EMB + k]) : 0.0f;
}
__global__ void prep_ih(const float* __restrict__ wf, const float* __restrict__ wb,
                        const float* __restrict__ b1f, const float* __restrict__ b2f,
                        const float* __restrict__ b1b, const float* __restrict__ b2b) {
    int np = blockIdx.x, dir = blockIdx.y;
    int r = (np & 3) * HID + (np >> 2);
    const float* w = dir ? wb : wf;
    for (int k = threadIdx.x; k < CVEC; k += blockDim.x)
        w_ih_t[dir][np * CVEC + k] = f2tf32f(w[r * CVEC + k]);
    if (threadIdx.x == 0)
        bias_comb[dir][np] = dir ? (b1b[r] + b2b[r]) : (b1f[r] + b2f[r]);
}
__global__ void prep_hh(const float* __restrict__ wf, const float* __restrict__ wb) {
    int np = blockIdx.x, dir = blockIdx.y;
    int r = (np & 3) * HID + (np >> 2);
    const float* w = dir ? wb : wf;
    for (int k = threadIdx.x; k < HID; k += blockDim.x)
        w_hh_t[dir][np * HID + k] = f2tf32f(w[r * HID + k]);
}
__global__ void prep_out(const float* __restrict__ w) {
    int n = blockIdx.x;
    for (int k = threadIdx.x; k < 2 * HID; k += blockDim.x)
        w_out_t[n * 2 * HID + k] = f2tf32f(w[n * 2 * HID + k]);
}

// ---------------- kernel: embedding + bilinear interp (tf32-rounded, padded) --
__global__ void interp_kernel(const int* __restrict__ words,
                              const int* __restrict__ lengths,
                              const float* __restrict__ emb) {
    int b = blockIdx.x;
    __shared__ int w0s[TT], w1s[TT];
    __shared__ float fs[TT];
    int tid = threadIdx.x;
    if (tid < TT) {
        int L = lengths[b];
        float Lf = (float)(L - 1);
        float pos = (float)tid * Lf / 9.0f;      // identical expr to reference
        int i0 = (int)floorf(pos);
        int i1 = min(i0 + 1, L - 1);
        fs[tid]  = pos - (float)i0;
        w0s[tid] = words[b * LMAX + i0];
        w1s[tid] = words[b * LMAX + i1];
    }
    __syncthreads();
    for (int e = tid; e < TT * EMBP; e += blockDim.x) {
        int t = e / EMBP, k = e - t * EMBP;
        float v = 0.0f;
        if (k < EMB) {
            float f = fs[t];
            v = f2tf32f(emb[w0s[t] * EMB + k] * (1.0f - f) + emb[w1s[t] * EMB + k] * f);
        }
        g_e[(size_t)(t * NB + b) * EMBP + k] = v;
    }
}

// ---------------- pipelined tf32 mma GEMM (dynamic smem, BKT=32) --------------
// MODE 0: g_cv = tf32(relu(g_e @ w_enc_t^T + bias))        K=320 N=256
// MODE 1: g_xg[dir] = g_cv @ w_ih_t[dir]^T + bias_comb     K=256 N=1024
//         dir = blockIdx.z (both directions fused in one launch);
//         bias/Cout params IGNORED — device globals resolved in-kernel.
// MODE 2: out = g_hcat @ w_out_t^T + bias  (scatter)       K=512 N=512
template <int MODE>
__global__ __launch_bounds__(256, 1)
void gemm_tc(const float* __restrict__ bias_in, float* __restrict__ Cout, int dir_in) {
    constexpr int K = (MODE == 0) ? EMBP : (MODE == 1 ? CVEC : 2 * HID);
    constexpr int N = (MODE == 0) ? CVEC : (MODE == 1 ? G4 : OUTD);
    constexpr int NIT = K / BKT;

    extern __shared__ __align__(16) float dynsmem[];
    float (*As)[BM][TILE_F] = reinterpret_cast<float (*)[BM][TILE_F]>(dynsmem);
    float (*Bs)[BN][TILE_F] =
        reinterpret_cast<float (*)[BN][TILE_F]>(dynsmem + 2 * BM * TILE_F);

    const int dir = (MODE == 1) ? (int)blockIdx.z : dir_in;
    const float* A  = (MODE == 0) ? g_e : (MODE == 1 ? g_cv : g_hcat);
    const float* Wt = (MODE == 0) ? w_enc_t : (MODE == 1 ? w_ih_t[dir] : w_out_t);
    // device-side resolution of device globals (host cannot pass their addresses)
    const float* bias = (MODE == 1) ? bias_comb[dir] : bias_in;
    float* C1 = (MODE == 1) ? g_xg[dir] : Cout;
    const int lda = K;

    int m0 = blockIdx.y * BM, n0 = blockIdx.x * BN;
    int tid = threadIdx.x;
    int lrow = tid >> 3, lcol = (tid & 7) * 4;     // 32 rows x 32 cols per pass
    const float* Abase = A + (size_t)(m0 + lrow) * lda + lcol;
    const float* Bbase = Wt + (size_t)(n0 + lrow) * K + lcol;

    auto load_tile = [&](int buf, int k0) {
#pragma unroll
        for (int i = 0; i < 4; i++) {
            cp16(&As[buf][lrow + 32 * i][lcol], Abase + (size_t)(32 * i) * lda + k0);
            cp16(&Bs[buf][lrow + 32 * i][lcol], Bbase + (size_t)(32 * i) * K + k0);
        }
    };

    int warp = tid >> 5, lane = tid & 31;
    int g = lane >> 2, tg = lane & 3;
    int wm = (warp >> 2) * 64, wn = (warp & 3) * 32;

    float acc[4][4][4] = {};

    load_tile(0, 0);
    cp_commit();

    for (int it = 0; it < NIT; ++it) {
        if (it + 1 < NIT) load_tile((it + 1) & 1, (it + 1) * BKT);
        cp_commit();
        cp_wait1();
        __syncthreads();
        int buf = it & 1;
#pragma unroll
        for (int ks = 0; ks < BKT; ks += 8) {
            unsigned a[4][4], b[4][2];
#pragma unroll
            for (int mi = 0; mi < 4; mi++) {
                int r = wm + 16 * mi;
                a[mi][0] = __float_as_uint(As[buf][r + g][ks + tg]);
                a[mi][1] = __float_as_uint(As[buf][r + g + 8][ks + tg]);
                a[mi][2] = __float_as_uint(As[buf][r + g][ks + tg + 4]);
                a[mi][3] = __float_as_uint(As[buf][r + g + 8][ks + tg + 4]);
            }
#pragma unroll
            for (int ni = 0; ni < 4; ni++) {
                int r = wn + 8 * ni + g;
                b[ni][0] = __float_as_uint(Bs[buf][r][ks + tg]);
                b[ni][1] = __float_as_uint(Bs[buf][r][ks + tg + 4]);
            }
#pragma unroll
            for (int mi = 0; mi < 4; mi++)
#pragma unroll
                for (int ni = 0; ni < 4; ni++)
                    mma_tf32(acc[mi][ni], a[mi], b[ni]);
        }
        __syncthreads();
    }

    // ---- epilogue ----
#pragma unroll
    for (int mi = 0; mi < 4; mi++) {
        int row = m0 + wm + 16 * mi + g;
#pragma unroll
        for (int ni = 0; ni < 4; ni++) {
            int col = n0 + wn + 8 * ni + 2 * tg;
            float* a4 = acc[mi][ni];
            float bb0 = bias[col], bb1 = bias[col + 1];
            if (MODE == 0) {
                g_cv[(size_t)row * N + col]           = f2tf32f(fmaxf(a4[0] + bb0, 0.f));
                g_cv[(size_t)row * N + col + 1]       = f2tf32f(fmaxf(a4[1] + bb1, 0.f));
                g_cv[(size_t)(row + 8) * N + col]     = f2tf32f(fmaxf(a4[2] + bb0, 0.f));
                g_cv[(size_t)(row + 8) * N + col + 1] = f2tf32f(fmaxf(a4[3] + bb1, 0.f));
            } else if (MODE == 1) {
                C1[(size_t)row * N + col]           = a4[0] + bb0;
                C1[(size_t)row * N + col + 1]       = a4[1] + bb1;
                C1[(size_t)(row + 8) * N + col]     = a4[2] + bb0;
                C1[(size_t)(row + 8) * N + col + 1] = a4[3] + bb1;
            } else {
                int t = row >> 13;              // NB = 8192
                int b = row & (NB - 1);
                size_t o1 = ((size_t)b * TT + t) * OUTD + col;
                size_t o2 = ((size_t)(b + 8) * TT + t) * OUTD + col;
                C1[o1]     = a4[0] + bb0;
                C1[o1 + 1] = a4[1] + bb1;
                C1[o2]     = a4[2] + bb0;
                C1[o2 + 1] = a4[3] + bb1;
            }
        }
    }
}

// ---------------- fused recurrent GEMM (pipelined tf32 mma) + LSTM cell -------
__global__ __launch_bounds__(256, 1)
void lstm_step_mma(int s) {
    int dir = blockIdx.z;
    int t = dir ? (TT - 1 - s) : s;
    int tprev = dir ? t + 1 : t - 1;
    const float* xg = g_xg[dir] + (size_t)t * NB * G4;
    float* hout = g_hcat + (size_t)t * NB * (2 * HID) + dir * HID;
    float* cs = g_cs[dir];

    extern __shared__ __align__(16) float dynsmem[];
    float (*As)[BM][TILE_F] = reinterpret_cast<float (*)[BM][TILE_F]>(dynsmem);
    float (*Bs)[BN][TILE_F] =
        reinterpret_cast<float (*)[BN][TILE_F]>(dynsmem + 2 * BM * TILE_F);

    int m0 = blockIdx.y * BM, n0 = blockIdx.x * BN;
    int tid = threadIdx.x;
    int warp = tid >> 5, lane = tid & 31;
    int g = lane >> 2, tg = lane & 3;
    int wm = (warp >> 2) * 64, wn = (warp & 3) * 32;

    float acc[4][4][4] = {};

    if (s > 0) {
        const float* A = g_hcat + (size_t)tprev * NB * (2 * HID) + dir * HID;
        const float* Wt = w_hh_t[dir];
        const int lda = 2 * HID;
        int lrow = tid >> 3, lcol = (tid & 7) * 4;
        const float* Abase = A + (size_t)(m0 + lrow) * lda + lcol;
        const float* Bbase = Wt + (size_t)(n0 + lrow) * HID + lcol;

        auto load_tile = [&](int buf, int k0) {
#pragma unroll
            for (int i = 0; i < 4; i++) {
                cp16(&As[buf][lrow + 32 * i][lcol], Abase + (size_t)(32 * i) * lda + k0);
                cp16(&Bs[buf][lrow + 32 * i][lcol], Bbase + (size_t)(32 * i) * HID + k0);
            }
        };
        constexpr int NIT = HID / BKT;
        load_tile(0, 0);
        cp_commit();
        for (int it = 0; it < NIT; ++it) {
            if (it + 1 < NIT) load_tile((it + 1) & 1, (it + 1) * BKT);
            cp_commit();
            cp_wait1();
            __syncthreads();
            int buf = it & 1;
#pragma unroll
            for (int ks = 0; ks < BKT; ks += 8) {
                unsigned a[4][4], b[4][2];
#pragma unroll
                for (int mi = 0; mi < 4; mi++) {
                    int r = wm + 16 * mi;
                    a[mi][0] = __float_as_uint(As[buf][r + g][ks + tg]);
                    a[mi][1] = __float_as_uint(As[buf][r + g + 8][ks + tg]);
                    a[mi][2] = __float_as_uint(As[buf][r + g][ks + tg + 4]);
                    a[mi][3] = __float_as_uint(As[buf][r + g + 8][ks + tg + 4]);
                }
#pragma unroll
                for (int ni = 0; ni < 4; ni++) {
                    int r = wn + 8 * ni + g;
                    b[ni][0] = __float_as_uint(Bs[buf][r][ks + tg]);
                    b[ni][1] = __float_as_uint(Bs[buf][r][ks + tg + 4]);
                }
#pragma unroll
                for (int mi = 0; mi < 4; mi++)
#pragma unroll
                    for (int ni = 0; ni < 4; ni++)
                        mma_tf32(acc[mi][ni], a[mi], b[ni]);
            }
            __syncthreads();
        }
    }

    // ---- fused LSTM cell epilogue (gate-permuted columns n'=4*hid+gate) ------
#pragma unroll
    for (int mi = 0; mi < 4; mi++) {
#pragma unroll
        for (int ni = 0; ni < 4; ni++) {
            float* a4 = acc[mi][ni];
            float s0 = __shfl_xor_sync(0xffffffffu, a4[0], 1);
            float s1 = __shfl_xor_sync(0xffffffffu, a4[1], 1);
            float s2 = __shfl_xor_sync(0xffffffffu, a4[2], 1);
            float s3 = __shfl_xor_sync(0xffffffffu, a4[3], 1);
            int odd = tg & 1;
            int j = ((n0 + wn + 8 * ni) >> 2) + (tg >> 1);   // hidden index 0..255
            int b = m0 + wm + 16 * mi + g + (odd ? 8 : 0);
            float gi, gf, gg, go;
            if (!odd) { gi = a4[0]; gf = a4[1]; gg = s0;    go = s1;    }
            else      { gi = s2;    gf = s3;    gg = a4[2]; go = a4[3]; }
            float4 xv = *(const float4*)&xg[(size_t)b * G4 + 4 * j];
            gi += xv.x; gf += xv.y; gg += xv.z; go += xv.w;
            float cp = (s > 0) ? cs[(size_t)b * HID + j] : 0.0f;
            float ii = 1.0f / (1.0f + expf(-gi));
            float ff = 1.0f / (1.0f + expf(-gf));
            float gt = tanhf(gg);
            float oo = 1.0f / (1.0f + expf(-go));
            float c = ff * cp + ii * gt;
            cs[(size_t)b * HID + j] = c;
            hout[(size_t)b * (2 * HID) + j] = f2tf32f(oo * tanhf(c));
        }
    }
}

// ---------------- launcher ---------------------------------------------------
extern "C" void kernel_launch(void* const* d_in, const int* in_sizes, int n_in,
                              void* d_out, int out_size) {
    const int*   words   = (const int*)d_in[0];
    const int*   lengths = (const int*)d_in[1];
    const float* emb     = (const float*)d_in[2];
    const float* enc_w   = (const float*)d_in[3];
    const float* enc_b   = (const float*)d_in[4];
    const float* wih_f   = (const float*)d_in[5];
    const float* whh_f   = (const float*)d_in[6];
    const float* bih_f   = (const float*)d_in[7];
    const float* bhh_f   = (const float*)d_in[8];
    const float* wih_b   = (const float*)d_in[9];
    const float* whh_b   = (const float*)d_in[10];
    const float* bih_b   = (const float*)d_in[11];
    const float* bhh_b   = (const float*)d_in[12];
    const float* out_w   = (const float*)d_in[13];
    const float* out_b   = (const float*)d_in[14];
    float* out = (float*)d_out;

    // opt-in to >48KB dynamic smem (host attribute set; no allocation, capturable;
    // verified to execute under the harness in R11)
    (void)cudaFuncSetAttribute(gemm_tc<0>, cudaFuncAttributeMaxDynamicSharedMemorySize, SMEM_BYTES);
    (void)cudaFuncSetAttribute(gemm_tc<1>, cudaFuncAttributeMaxDynamicSharedMemorySize, SMEM_BYTES);
    (void)cudaFuncSetAttribute(gemm_tc<2>, cudaFuncAttributeMaxDynamicSharedMemorySize, SMEM_BYTES);
    (void)cudaFuncSetAttribute(lstm_step_mma, cudaFuncAttributeMaxDynamicSharedMemorySize, SMEM_BYTES);

    const int M = TT * NB;  // 81920

    prep_enc<<<CVEC, 256>>>(enc_w);
    prep_ih<<<dim3(G4, 2), 256>>>(wih_f, wih_b, bih_f, bhh_f, bih_b, bhh_b);
    prep_hh<<<dim3(G4, 2), 256>>>(whh_f, whh_b);
    prep_out<<<OUTD, 256>>>(out_w);

    interp_kernel<<<NB, 256>>>(words, lengths, emb);

    gemm_tc<0><<<dim3(CVEC / BN, M / BM), 256, SMEM_BYTES>>>(enc_b, (float*)0, 0);
    gemm_tc<1><<<dim3(G4 / BN, M / BM, 2), 256, SMEM_BYTES>>>((const float*)0, (float*)0, 0);

    for (int s = 0; s < TT; s++) {
        lstm_step_mma<<<dim3(G4 / BN, NB / BM, 2), 256, SMEM_BYTES>>>(s);
    }

    gemm_tc<2><<<dim3(OUTD / BN, M / BM), 256, SMEM_BYTES>>>(out_b, out, 0);
}

// round 16
// speedup vs baseline: 1.1712x; 1.1712x over previous
#include <cuda_runtime.h>
#include <math.h>
#include <stdint.h>

#define NB   8192
#define LMAX 12
#define TT   10
#define EMB  300
#define EMBP 320      // padded to multiple of 32
#define CVEC 256
#define HID  256
#define OUTD 512
#define G4   1024     // 4*HID

#define BM 128
#define BN 128
#define BKT 16
#define SPAD 4
#define TILE_F (BKT + SPAD)
// static smem: As[2][BM][TILE_F] + Bs[2][BN][TILE_F] = 40960 bytes (< 48KB)
// with __launch_bounds__(256,2): 2 CTAs/SM -> 80KB smem, 2x64K... regs capped at 128

// ---------------- scratch (static device globals; no allocations) ------------
__device__ __align__(128) float g_e   [TT * NB * EMBP];     // tf32-rounded, padded
__device__ __align__(128) float g_cv  [TT * NB * CVEC];     // tf32-rounded
__device__ __align__(128) float g_xg  [2][TT * NB * G4];    // fp32, gate-permuted n'=4*hid+gate
__device__ __align__(128) float g_hcat[TT * NB * 2 * HID];  // tf32-rounded; [t][b][dir*256+j]
__device__ __align__(128) float g_cs  [2][NB * HID];        // fp32 cell state
// pre-rounded / pre-permuted weights
__device__ __align__(128) float w_enc_t[CVEC * EMBP];
__device__ __align__(128) float w_ih_t [2][G4 * CVEC];
__device__ __align__(128) float w_hh_t [2][G4 * HID];
__device__ __align__(128) float w_out_t[OUTD * 2 * HID];
__device__ __align__(128) float bias_comb[2][G4];

// ---------------- helpers ----------------------------------------------------
__device__ __forceinline__ float f2tf32f(float x) {
    unsigned r;
    asm("cvt.rna.tf32.f32 %0, %1;" : "=r"(r) : "f"(x));
    return __uint_as_float(r);
}

__device__ __forceinline__ void mma_tf32(float* d, const unsigned* a, const unsigned* b) {
    asm volatile(
        "mma.sync.aligned.m16n8k8.row.col.f32.tf32.tf32.f32 "
        "{%0,%1,%2,%3}, {%4,%5,%6,%7}, {%8,%9}, {%0,%1,%2,%3};"
        : "+f"(d[0]), "+f"(d[1]), "+f"(d[2]), "+f"(d[3])
        : "r"(a[0]), "r"(a[1]), "r"(a[2]), "r"(a[3]), "r"(b[0]), "r"(b[1]));
}

__device__ __forceinline__ void cp16(void* smem_dst, const void* gsrc) {
    uint32_t d = (uint32_t)__cvta_generic_to_shared(smem_dst);
    asm volatile("cp.async.cg.shared.global [%0], [%1], 16;\n" :: "r"(d), "l"(gsrc));
}
__device__ __forceinline__ void cp_commit() { asm volatile("cp.async.commit_group;\n"); }
__device__ __forceinline__ void cp_wait1()  { asm volatile("cp.async.wait_group 1;\n"); }

// ---------------- prep kernels (tiny; run inside graph each call) -------------
__global__ void prep_enc(const float* __restrict__ w) {
    int n = blockIdx.x;
    for (int k = threadIdx.x; k < EMBP; k += blockDim.x)
        w_enc_t[n * EMBP + k] = (k < EMB) ? f2tf32f(w[n * EMB + k]) : 0.0f;
}
__global__ void prep_ih(const float* __restrict__ wf, const float* __restrict__ wb,
                        const float* __restrict__ b1f, const float* __restrict__ b2f,
                        const float* __restrict__ b1b, const float* __restrict__ b2b) {
    int np = blockIdx.x, dir = blockIdx.y;
    int r = (np & 3) * HID + (np >> 2);
    const float* w = dir ? wb : wf;
    for (int k = threadIdx.x; k < CVEC; k += blockDim.x)
        w_ih_t[dir][np * CVEC + k] = f2tf32f(w[r * CVEC + k]);
    if (threadIdx.x == 0)
        bias_comb[dir][np] = dir ? (b1b[r] + b2b[r]) : (b1f[r] + b2f[r]);
}
__global__ void prep_hh(const float* __restrict__ wf, const float* __restrict__ wb) {
    int np = blockIdx.x, dir = blockIdx.y;
    int r = (np & 3) * HID + (np >> 2);
    const float* w = dir ? wb : wf;
    for (int k = threadIdx.x; k < HID; k += blockDim.x)
        w_hh_t[dir][np * HID + k] = f2tf32f(w[r * HID + k]);
}
__global__ void prep_out(const float* __restrict__ w) {
    int n = blockIdx.x;
    for (int k = threadIdx.x; k < 2 * HID; k += blockDim.x)
        w_out_t[n * 2 * HID + k] = f2tf32f(w[n * 2 * HID + k]);
}

// ---------------- kernel: embedding + bilinear interp (tf32-rounded, padded) --
__global__ void interp_kernel(const int* __restrict__ words,
                              const int* __restrict__ lengths,
                              const float* __restrict__ emb) {
    int b = blockIdx.x;
    __shared__ int w0s[TT], w1s[TT];
    __shared__ float fs[TT];
    int tid = threadIdx.x;
    if (tid < TT) {
        int L = lengths[b];
        float Lf = (float)(L - 1);
        float pos = (float)tid * Lf / 9.0f;      // identical expr to reference
        int i0 = (int)floorf(pos);
        int i1 = min(i0 + 1, L - 1);
        fs[tid]  = pos - (float)i0;
        w0s[tid] = words[b * LMAX + i0];
        w1s[tid] = words[b * LMAX + i1];
    }
    __syncthreads();
    for (int e = tid; e < TT * EMBP; e += blockDim.x) {
        int t = e / EMBP, k = e - t * EMBP;
        float v = 0.0f;
        if (k < EMB) {
            float f = fs[t];
            v = f2tf32f(emb[w0s[t] * EMB + k] * (1.0f - f) + emb[w1s[t] * EMB + k] * f);
        }
        g_e[(size_t)(t * NB + b) * EMBP + k] = v;
    }
}

// ---------------- pipelined tf32 mma GEMM (static smem, 2 CTAs/SM) ------------
// MODE 0: g_cv = tf32(relu(g_e @ w_enc_t^T + bias))        K=320 N=256
// MODE 1: g_xg[dir] = g_cv @ w_ih_t[dir]^T + bias_comb     K=256 N=1024
//         (bias/Cout params IGNORED for MODE 1; device globals resolved in-kernel)
// MODE 2: out = g_hcat @ w_out_t^T + bias  (scatter)       K=512 N=512
template <int MODE>
__global__ __launch_bounds__(256, 2)
void gemm_tc(const float* __restrict__ bias_in, float* __restrict__ Cout, int dir) {
    constexpr int K = (MODE == 0) ? EMBP : (MODE == 1 ? CVEC : 2 * HID);
    constexpr int N = (MODE == 0) ? CVEC : (MODE == 1 ? G4 : OUTD);
    constexpr int NIT = K / BKT;

    __shared__ __align__(16) float As[2][BM][TILE_F];
    __shared__ __align__(16) float Bs[2][BN][TILE_F];

    const float* A  = (MODE == 0) ? g_e : (MODE == 1 ? g_cv : g_hcat);
    const float* Wt = (MODE == 0) ? w_enc_t : (MODE == 1 ? w_ih_t[dir] : w_out_t);
    // device-side resolution of device globals (host cannot pass their addresses)
    const float* bias = (MODE == 1) ? bias_comb[dir] : bias_in;
    float* C1 = (MODE == 1) ? g_xg[dir] : Cout;
    const int lda = K;

    int m0 = blockIdx.y * BM, n0 = blockIdx.x * BN;
    int tid = threadIdx.x;
    int lrow = tid >> 2, lcol = (tid & 3) * 4;     // 64 rows x 16 cols per pass
    const float* Abase = A + (size_t)(m0 + lrow) * lda + lcol;
    const float* Bbase = Wt + (size_t)(n0 + lrow) * K + lcol;

    auto load_tile = [&](int buf, int k0) {
#pragma unroll
        for (int i = 0; i < 2; i++) {
            cp16(&As[buf][lrow + 64 * i][lcol], Abase + (size_t)(64 * i) * lda + k0);
            cp16(&Bs[buf][lrow + 64 * i][lcol], Bbase + (size_t)(64 * i) * K + k0);
        }
    };

    int warp = tid >> 5, lane = tid & 31;
    int g = lane >> 2, tg = lane & 3;
    int wm = (warp >> 2) * 64, wn = (warp & 3) * 32;

    float acc[4][4][4] = {};

    load_tile(0, 0);
    cp_commit();

    for (int it = 0; it < NIT; ++it) {
        if (it + 1 < NIT) load_tile((it + 1) & 1, (it + 1) * BKT);
        cp_commit();
        cp_wait1();
        __syncthreads();
        int buf = it & 1;
#pragma unroll
        for (int ks = 0; ks < BKT; ks += 8) {
            unsigned a[4][4], b[4][2];
#pragma unroll
            for (int mi = 0; mi < 4; mi++) {
                int r = wm + 16 * mi;
                a[mi][0] = __float_as_uint(As[buf][r + g][ks + tg]);
                a[mi][1] = __float_as_uint(As[buf][r + g + 8][ks + tg]);
                a[mi][2] = __float_as_uint(As[buf][r + g][ks + tg + 4]);
                a[mi][3] = __float_as_uint(As[buf][r + g + 8][ks + tg + 4]);
            }
#pragma unroll
            for (int ni = 0; ni < 4; ni++) {
                int r = wn + 8 * ni + g;
                b[ni][0] = __float_as_uint(Bs[buf][r][ks + tg]);
                b[ni][1] = __float_as_uint(Bs[buf][r][ks + tg + 4]);
            }
#pragma unroll
            for (int mi = 0; mi < 4; mi++)
#pragma unroll
                for (int ni = 0; ni < 4; ni++)
                    mma_tf32(acc[mi][ni], a[mi], b[ni]);
        }
        __syncthreads();
    }

    // ---- epilogue ----
#pragma unroll
    for (int mi = 0; mi < 4; mi++) {
        int row = m0 + wm + 16 * mi + g;
#pragma unroll
        for (int ni = 0; ni < 4; ni++) {
            int col = n0 + wn + 8 * ni + 2 * tg;
            float* a4 = acc[mi][ni];
            float bb0 = bias[col], bb1 = bias[col + 1];
            if (MODE == 0) {
                g_cv[(size_t)row * N + col]           = f2tf32f(fmaxf(a4[0] + bb0, 0.f));
                g_cv[(size_t)row * N + col + 1]       = f2tf32f(fmaxf(a4[1] + bb1, 0.f));
                g_cv[(size_t)(row + 8) * N + col]     = f2tf32f(fmaxf(a4[2] + bb0, 0.f));
                g_cv[(size_t)(row + 8) * N + col + 1] = f2tf32f(fmaxf(a4[3] + bb1, 0.f));
            } else if (MODE == 1) {
                C1[(size_t)row * N + col]           = a4[0] + bb0;
                C1[(size_t)row * N + col + 1]       = a4[1] + bb1;
                C1[(size_t)(row + 8) * N + col]     = a4[2] + bb0;
                C1[(size_t)(row + 8) * N + col + 1] = a4[3] + bb1;
            } else {
                int t = row >> 13;              // NB = 8192
                int b = row & (NB - 1);
                size_t o1 = ((size_t)b * TT + t) * OUTD + col;
                size_t o2 = ((size_t)(b + 8) * TT + t) * OUTD + col;
                C1[o1]     = a4[0] + bb0;
                C1[o1 + 1] = a4[1] + bb1;
                C1[o2]     = a4[2] + bb0;
                C1[o2 + 1] = a4[3] + bb1;
            }
        }
    }
}

// ---------------- fused recurrent GEMM (pipelined tf32 mma) + LSTM cell -------
__global__ __launch_bounds__(256, 2)
void lstm_step_mma(int s) {
    int dir = blockIdx.z;
    int t = dir ? (TT - 1 - s) : s;
    int tprev = dir ? t + 1 : t - 1;
    const float* xg = g_xg[dir] + (size_t)t * NB * G4;
    float* hout = g_hcat + (size_t)t * NB * (2 * HID) + dir * HID;
    float* cs = g_cs[dir];

    __shared__ __align__(16) float As[2][BM][TILE_F];
    __shared__ __align__(16) float Bs[2][BN][TILE_F];

    int m0 = blockIdx.y * BM, n0 = blockIdx.x * BN;
    int tid = threadIdx.x;
    int warp = tid >> 5, lane = tid & 31;
    int g = lane >> 2, tg = lane & 3;
    int wm = (warp >> 2) * 64, wn = (warp & 3) * 32;

    float acc[4][4][4] = {};

    if (s > 0) {
        const float* A = g_hcat + (size_t)tprev * NB * (2 * HID) + dir * HID;
        const float* Wt = w_hh_t[dir];
        const int lda = 2 * HID;
        int lrow = tid >> 2, lcol = (tid & 3) * 4;
        const float* Abase = A + (size_t)(m0 + lrow) * lda + lcol;
        const float* Bbase = Wt + (size_t)(n0 + lrow) * HID + lcol;

        auto load_tile = [&](int buf, int k0) {
#pragma unroll
            for (int i = 0; i < 2; i++) {
                cp16(&As[buf][lrow + 64 * i][lcol], Abase + (size_t)(64 * i) * lda + k0);
                cp16(&Bs[buf][lrow + 64 * i][lcol], Bbase + (size_t)(64 * i) * HID + k0);
            }
        };
        constexpr int NIT = HID / BKT;
        load_tile(0, 0);
        cp_commit();
        for (int it = 0; it < NIT; ++it) {
            if (it + 1 < NIT) load_tile((it + 1) & 1, (it + 1) * BKT);
            cp_commit();
            cp_wait1();
            __syncthreads();
            int buf = it & 1;
#pragma unroll
            for (int ks = 0; ks < BKT; ks += 8) {
                unsigned a[4][4], b[4][2];
#pragma unroll
                for (int mi = 0; mi < 4; mi++) {
                    int r = wm + 16 * mi;
                    a[mi][0] = __float_as_uint(As[buf][r + g][ks + tg]);
                    a[mi][1] = __float_as_uint(As[buf][r + g + 8][ks + tg]);
                    a[mi][2] = __float_as_uint(As[buf][r + g][ks + tg + 4]);
                    a[mi][3] = __float_as_uint(As[buf][r + g + 8][ks + tg + 4]);
                }
#pragma unroll
                for (int ni = 0; ni < 4; ni++) {
                    int r = wn + 8 * ni + g;
                    b[ni][0] = __float_as_uint(Bs[buf][r][ks + tg]);
                    b[ni][1] = __float_as_uint(Bs[buf][r][ks + tg + 4]);
                }
#pragma unroll
                for (int mi = 0; mi < 4; mi++)
#pragma unroll
                    for (int ni = 0; ni < 4; ni++)
                        mma_tf32(acc[mi][ni], a[mi], b[ni]);
            }
            __syncthreads();
        }
    }

    // ---- fused LSTM cell epilogue (gate-permuted columns n'=4*hid+gate) ------
#pragma unroll
    for (int mi = 0; mi < 4; mi++) {
#pragma unroll
        for (int ni = 0; ni < 4; ni++) {
            float* a4 = acc[mi][ni];
            float s0 = __shfl_xor_sync(0xffffffffu, a4[0], 1);
            float s1 = __shfl_xor_sync(0xffffffffu, a4[1], 1);
            float s2 = __shfl_xor_sync(0xffffffffu, a4[2], 1);
            float s3 = __shfl_xor_sync(0xffffffffu, a4[3], 1);
            int odd = tg & 1;
            int j = ((n0 + wn + 8 * ni) >> 2) + (tg >> 1);   // hidden index 0..255
            int b = m0 + wm + 16 * mi + g + (odd ? 8 : 0);
            float gi, gf, gg, go;
            if (!odd) { gi = a4[0]; gf = a4[1]; gg = s0;    go = s1;    }
            else      { gi = s2;    gf = s3;    gg = a4[2]; go = a4[3]; }
            float4 xv = *(const float4*)&xg[(size_t)b * G4 + 4 * j];
            gi += xv.x; gf += xv.y; gg += xv.z; go += xv.w;
            float cp = (s > 0) ? cs[(size_t)b * HID + j] : 0.0f;
            float ii = 1.0f / (1.0f + expf(-gi));
            float ff = 1.0f / (1.0f + expf(-gf));
            float gt = tanhf(gg);
            float oo = 1.0f / (1.0f + expf(-go));
            float c = ff * cp + ii * gt;
            cs[(size_t)b * HID + j] = c;
            hout[(size_t)b * (2 * HID) + j] = f2tf32f(oo * tanhf(c));
        }
    }
}

// ---------------- launcher ---------------------------------------------------
extern "C" void kernel_launch(void* const* d_in, const int* in_sizes, int n_in,
                              void* d_out, int out_size) {
    const int*   words   = (const int*)d_in[0];
    const int*   lengths = (const int*)d_in[1];
    const float* emb     = (const float*)d_in[2];
    const float* enc_w   = (const float*)d_in[3];
    const float* enc_b   = (const float*)d_in[4];
    const float* wih_f   = (const float*)d_in[5];
    const float* whh_f   = (const float*)d_in[6];
    const float* bih_f   = (const float*)d_in[7];
    const float* bhh_f   = (const float*)d_in[8];
    const float* wih_b   = (const float*)d_in[9];
    const float* whh_b   = (const float*)d_in[10];
    const float* bih_b   = (const float*)d_in[11];
    const float* bhh_b   = (const float*)d_in[12];
    const float* out_w   = (const float*)d_in[13];
    const float* out_b   = (const float*)d_in[14];
    float* out = (float*)d_out;

    const int M = TT * NB;  // 81920

    prep_enc<<<CVEC, 256>>>(enc_w);
    prep_ih<<<dim3(G4, 2), 256>>>(wih_f, wih_b, bih_f, bhh_f, bih_b, bhh_b);
    prep_hh<<<dim3(G4, 2), 256>>>(whh_f, whh_b);
    prep_out<<<OUTD, 256>>>(out_w);

    interp_kernel<<<NB, 256>>>(words, lengths, emb);

    gemm_tc<0><<<dim3(CVEC / BN, M / BM), 256>>>(enc_b, (float*)0, 0);
    gemm_tc<1><<<dim3(G4 / BN, M / BM), 256>>>((const float*)0, (float*)0, 0);
    gemm_tc<1><<<dim3(G4 / BN, M / BM), 256>>>((const float*)0, (float*)0, 1);

    for (int s = 0; s < TT; s++) {
        lstm_step_mma<<<dim3(G4 / BN, NB / BM, 2), 256>>>(s);
    }

    gemm_tc<2><<<dim3(OUTD / BN, M / BM), 256>>>(out_b, out, 0);
}

// round 17
// speedup vs baseline: 1.2132x; 1.0359x over previous
#include <cuda_runtime.h>
#include <math.h>
#include <stdint.h>

#define NB   8192
#define LMAX 12
#define TT   10
#define EMB  300
#define EMBP 320      // padded to multiple of 32
#define CVEC 256
#define HID  256
#define OUTD 512
#define G4   1024     // 4*HID

#define BM 128
#define BN 128
#define BKT 16
#define SPAD 4
#define TILE_F (BKT + SPAD)
// static smem: As[2][BM][TILE_F] + Bs[2][BN][TILE_F] = 40960 bytes (< 48KB)

// ---------------- scratch (static device globals; no allocations) ------------
__device__ __align__(128) float g_e   [TT * NB * EMBP];     // tf32-rounded, padded
__device__ __align__(128) float g_cv  [TT * NB * CVEC];     // tf32-rounded
__device__ __align__(128) float g_xg  [2][TT * NB * G4];    // fp32, gate-permuted n'=4*hid+gate
__device__ __align__(128) float g_hcat[TT * NB * 2 * HID];  // tf32-rounded; [t][b][dir*256+j]
__device__ __align__(128) float g_cs  [2][NB * HID];        // fp32 cell state
// pre-rounded / pre-permuted weights
__device__ __align__(128) float w_enc_t[CVEC * EMBP];
__device__ __align__(128) float w_ih_t [2][G4 * CVEC];
__device__ __align__(128) float w_hh_t [2][G4 * HID];
__device__ __align__(128) float w_out_t[OUTD * 2 * HID];
__device__ __align__(128) float bias_comb[2][G4];

// ---------------- helpers ----------------------------------------------------
__device__ __forceinline__ float f2tf32f(float x) {
    unsigned r;
    asm("cvt.rna.tf32.f32 %0, %1;" : "=r"(r) : "f"(x));
    return __uint_as_float(r);
}

__device__ __forceinline__ void mma_tf32(float* d, const unsigned* a, const unsigned* b) {
    asm volatile(
        "mma.sync.aligned.m16n8k8.row.col.f32.tf32.tf32.f32 "
        "{%0,%1,%2,%3}, {%4,%5,%6,%7}, {%8,%9}, {%0,%1,%2,%3};"
        : "+f"(d[0]), "+f"(d[1]), "+f"(d[2]), "+f"(d[3])
        : "r"(a[0]), "r"(a[1]), "r"(a[2]), "r"(a[3]), "r"(b[0]), "r"(b[1]));
}

__device__ __forceinline__ void ldsm4(unsigned& r0, unsigned& r1, unsigned& r2, unsigned& r3,
                                      uint32_t addr) {
    asm volatile("ldmatrix.sync.aligned.m8n8.x4.shared.b16 {%0,%1,%2,%3}, [%4];"
                 : "=r"(r0), "=r"(r1), "=r"(r2), "=r"(r3) : "r"(addr));
}

__device__ __forceinline__ void cp16(void* smem_dst, const void* gsrc) {
    uint32_t d = (uint32_t)__cvta_generic_to_shared(smem_dst);
    asm volatile("cp.async.cg.shared.global [%0], [%1], 16;\n" :: "r"(d), "l"(gsrc));
}
__device__ __forceinline__ void cp_commit() { asm volatile("cp.async.commit_group;\n"); }
__device__ __forceinline__ void cp_wait1()  { asm volatile("cp.async.wait_group 1;\n"); }

// ---------------- prep kernels (tiny; run inside graph each call) -------------
__global__ void prep_enc(const float* __restrict__ w) {
    int n = blockIdx.x;
    for (int k = threadIdx.x; k < EMBP; k += blockDim.x)
        w_enc_t[n * EMBP + k] = (k < EMB) ? f2tf32f(w[n * EMB + k]) : 0.0f;
}
__global__ void prep_ih(const float* __restrict__ wf, const float* __restrict__ wb,
                        const float* __restrict__ b1f, const float* __restrict__ b2f,
                        const float* __restrict__ b1b, const float* __restrict__ b2b) {
    int np = blockIdx.x, dir = blockIdx.y;
    int r = (np & 3) * HID + (np >> 2);
    const float* w = dir ? wb : wf;
    for (int k = threadIdx.x; k < CVEC; k += blockDim.x)
        w_ih_t[dir][np * CVEC + k] = f2tf32f(w[r * CVEC + k]);
    if (threadIdx.x == 0)
        bias_comb[dir][np] = dir ? (b1b[r] + b2b[r]) : (b1f[r] + b2f[r]);
}
__global__ void prep_hh(const float* __restrict__ wf, const float* __restrict__ wb) {
    int np = blockIdx.x, dir = blockIdx.y;
    int r = (np & 3) * HID + (np >> 2);
    const float* w = dir ? wb : wf;
    for (int k = threadIdx.x; k < HID; k += blockDim.x)
        w_hh_t[dir][np * HID + k] = f2tf32f(w[r * HID + k]);
}
__global__ void prep_out(const float* __restrict__ w) {
    int n = blockIdx.x;
    for (int k = threadIdx.x; k < 2 * HID; k += blockDim.x)
        w_out_t[n * 2 * HID + k] = f2tf32f(w[n * 2 * HID + k]);
}

// ---------------- kernel: embedding + bilinear interp (tf32-rounded, padded) --
__global__ void interp_kernel(const int* __restrict__ words,
                              const int* __restrict__ lengths,
                              const float* __restrict__ emb) {
    int b = blockIdx.x;
    __shared__ int w0s[TT], w1s[TT];
    __shared__ float fs[TT];
    int tid = threadIdx.x;
    if (tid < TT) {
        int L = lengths[b];
        float Lf = (float)(L - 1);
        float pos = (float)tid * Lf / 9.0f;      // identical expr to reference
        int i0 = (int)floorf(pos);
        int i1 = min(i0 + 1, L - 1);
        fs[tid]  = pos - (float)i0;
        w0s[tid] = words[b * LMAX + i0];
        w1s[tid] = words[b * LMAX + i1];
    }
    __syncthreads();
    for (int e = tid; e < TT * EMBP; e += blockDim.x) {
        int t = e / EMBP, k = e - t * EMBP;
        float v = 0.0f;
        if (k < EMB) {
            float f = fs[t];
            v = f2tf32f(emb[w0s[t] * EMB + k] * (1.0f - f) + emb[w1s[t] * EMB + k] * f);
        }
        g_e[(size_t)(t * NB + b) * EMBP + k] = v;
    }
}

// ---------------- pipelined tf32 mma GEMM (static smem, LDSM frags) -----------
// MODE 0: g_cv = tf32(relu(g_e @ w_enc_t^T + bias))        K=320 N=256
// MODE 1: g_xg[dir] = g_cv @ w_ih_t[dir]^T + bias_comb     K=256 N=1024
//         (bias/Cout params IGNORED for MODE 1; device globals resolved in-kernel)
// MODE 2: out = g_hcat @ w_out_t^T + bias  (scatter)       K=512 N=512
template <int MODE>
__global__ __launch_bounds__(256, 2)
void gemm_tc(const float* __restrict__ bias_in, float* __restrict__ Cout, int dir) {
    constexpr int K = (MODE == 0) ? EMBP : (MODE == 1 ? CVEC : 2 * HID);
    constexpr int N = (MODE == 0) ? CVEC : (MODE == 1 ? G4 : OUTD);
    constexpr int NIT = K / BKT;

    __shared__ __align__(16) float As[2][BM][TILE_F];
    __shared__ __align__(16) float Bs[2][BN][TILE_F];

    const float* A  = (MODE == 0) ? g_e : (MODE == 1 ? g_cv : g_hcat);
    const float* Wt = (MODE == 0) ? w_enc_t : (MODE == 1 ? w_ih_t[dir] : w_out_t);
    // device-side resolution of device globals (host cannot pass their addresses)
    const float* bias = (MODE == 1) ? bias_comb[dir] : bias_in;
    float* C1 = (MODE == 1) ? g_xg[dir] : Cout;
    const int lda = K;

    int m0 = blockIdx.y * BM, n0 = blockIdx.x * BN;
    int tid = threadIdx.x;
    int lrow = tid >> 2, lcol = (tid & 3) * 4;     // 64 rows x 16 cols per pass
    const float* Abase = A + (size_t)(m0 + lrow) * lda + lcol;
    const float* Bbase = Wt + (size_t)(n0 + lrow) * K + lcol;

    auto load_tile = [&](int buf, int k0) {
#pragma unroll
        for (int i = 0; i < 2; i++) {
            cp16(&As[buf][lrow + 64 * i][lcol], Abase + (size_t)(64 * i) * lda + k0);
            cp16(&Bs[buf][lrow + 64 * i][lcol], Bbase + (size_t)(64 * i) * K + k0);
        }
    };

    int warp = tid >> 5, lane = tid & 31;
    int g = lane >> 2, tg = lane & 3;
    int wm = (warp >> 2) * 64, wn = (warp & 3) * 32;

    // LDSM lane->address mapping (b32 8x4 matrices, 4 per ldmatrix.x4)
    uint32_t As_base = (uint32_t)__cvta_generic_to_shared(&As[0][0][0]);
    uint32_t Bs_base = (uint32_t)__cvta_generic_to_shared(&Bs[0][0][0]);
    int arow = ((lane >> 3) & 1) * 8 + (lane & 7);
    int acol = (lane >> 4) * 4;
    int brow = (lane >> 4) * 8 + (lane & 7);
    int bcol = ((lane >> 3) & 1) * 4;
    uint32_t aaddr[4], baddr[2];
#pragma unroll
    for (int mi = 0; mi < 4; mi++)
        aaddr[mi] = As_base + (uint32_t)(((wm + 16 * mi + arow) * TILE_F + acol) * 4);
#pragma unroll
    for (int p = 0; p < 2; p++)
        baddr[p] = Bs_base + (uint32_t)(((wn + 16 * p + brow) * TILE_F + bcol) * 4);
    const uint32_t bufAoff = BM * TILE_F * 4;
    const uint32_t bufBoff = BN * TILE_F * 4;

    float acc[4][4][4] = {};

    load_tile(0, 0);
    cp_commit();

    for (int it = 0; it < NIT; ++it) {
        if (it + 1 < NIT) load_tile((it + 1) & 1, (it + 1) * BKT);
        cp_commit();
        cp_wait1();
        __syncthreads();
        int buf = it & 1;
        uint32_t aoff = buf * bufAoff, boff = buf * bufBoff;
#pragma unroll
        for (int ks = 0; ks < BKT; ks += 8) {
            unsigned a[4][4], b[2][4];
#pragma unroll
            for (int mi = 0; mi < 4; mi++)
                ldsm4(a[mi][0], a[mi][1], a[mi][2], a[mi][3], aaddr[mi] + aoff + ks * 4);
#pragma unroll
            for (int p = 0; p < 2; p++)
                ldsm4(b[p][0], b[p][1], b[p][2], b[p][3], baddr[p] + boff + ks * 4);
#pragma unroll
            for (int mi = 0; mi < 4; mi++)
#pragma unroll
                for (int ni = 0; ni < 4; ni++)
                    mma_tf32(acc[mi][ni], a[mi], &b[ni >> 1][(ni & 1) * 2]);
        }
        __syncthreads();
    }

    // ---- epilogue ----
#pragma unroll
    for (int mi = 0; mi < 4; mi++) {
        int row = m0 + wm + 16 * mi + g;
#pragma unroll
        for (int ni = 0; ni < 4; ni++) {
            int col = n0 + wn + 8 * ni + 2 * tg;
            float* a4 = acc[mi][ni];
            float bb0 = bias[col], bb1 = bias[col + 1];
            if (MODE == 0) {
                g_cv[(size_t)row * N + col]           = f2tf32f(fmaxf(a4[0] + bb0, 0.f));
                g_cv[(size_t)row * N + col + 1]       = f2tf32f(fmaxf(a4[1] + bb1, 0.f));
                g_cv[(size_t)(row + 8) * N + col]     = f2tf32f(fmaxf(a4[2] + bb0, 0.f));
                g_cv[(size_t)(row + 8) * N + col + 1] = f2tf32f(fmaxf(a4[3] + bb1, 0.f));
            } else if (MODE == 1) {
                C1[(size_t)row * N + col]           = a4[0] + bb0;
                C1[(size_t)row * N + col + 1]       = a4[1] + bb1;
                C1[(size_t)(row + 8) * N + col]     = a4[2] + bb0;
                C1[(size_t)(row + 8) * N + col + 1] = a4[3] + bb1;
            } else {
                int t = row >> 13;              // NB = 8192
                int b = row & (NB - 1);
                size_t o1 = ((size_t)b * TT + t) * OUTD + col;
                size_t o2 = ((size_t)(b + 8) * TT + t) * OUTD + col;
                C1[o1]     = a4[0] + bb0;
                C1[o1 + 1] = a4[1] + bb1;
                C1[o2]     = a4[2] + bb0;
                C1[o2 + 1] = a4[3] + bb1;
            }
        }
    }
}

// ---------------- fused recurrent GEMM (pipelined tf32 mma) + LSTM cell -------
__global__ __launch_bounds__(256, 2)
void lstm_step_mma(int s) {
    int dir = blockIdx.z;
    int t = dir ? (TT - 1 - s) : s;
    int tprev = dir ? t + 1 : t - 1;
    const float* xg = g_xg[dir] + (size_t)t * NB * G4;
    float* hout = g_hcat + (size_t)t * NB * (2 * HID) + dir * HID;
    float* cs = g_cs[dir];

    __shared__ __align__(16) float As[2][BM][TILE_F];
    __shared__ __align__(16) float Bs[2][BN][TILE_F];

    int m0 = blockIdx.y * BM, n0 = blockIdx.x * BN;
    int tid = threadIdx.x;
    int warp = tid >> 5, lane = tid & 31;
    int g = lane >> 2, tg = lane & 3;
    int wm = (warp >> 2) * 64, wn = (warp & 3) * 32;

    float acc[4][4][4] = {};

    if (s > 0) {
        const float* A = g_hcat + (size_t)tprev * NB * (2 * HID) + dir * HID;
        const float* Wt = w_hh_t[dir];
        const int lda = 2 * HID;
        int lrow = tid >> 2, lcol = (tid & 3) * 4;
        const float* Abase = A + (size_t)(m0 + lrow) * lda + lcol;
        const float* Bbase = Wt + (size_t)(n0 + lrow) * HID + lcol;

        auto load_tile = [&](int buf, int k0) {
#pragma unroll
            for (int i = 0; i < 2; i++) {
                cp16(&As[buf][lrow + 64 * i][lcol], Abase + (size_t)(64 * i) * lda + k0);
                cp16(&Bs[buf][lrow + 64 * i][lcol], Bbase + (size_t)(64 * i) * HID + k0);
            }
        };

        uint32_t As_base = (uint32_t)__cvta_generic_to_shared(&As[0][0][0]);
        uint32_t Bs_base = (uint32_t)__cvta_generic_to_shared(&Bs[0][0][0]);
        int arow = ((lane >> 3) & 1) * 8 + (lane & 7);
        int acol = (lane >> 4) * 4;
        int brow = (lane >> 4) * 8 + (lane & 7);
        int bcol = ((lane >> 3) & 1) * 4;
        uint32_t aaddr[4], baddr[2];
#pragma unroll
        for (int mi = 0; mi < 4; mi++)
            aaddr[mi] = As_base + (uint32_t)(((wm + 16 * mi + arow) * TILE_F + acol) * 4);
#pragma unroll
        for (int p = 0; p < 2; p++)
            baddr[p] = Bs_base + (uint32_t)(((wn + 16 * p + brow) * TILE_F + bcol) * 4);
        const uint32_t bufAoff = BM * TILE_F * 4;
        const uint32_t bufBoff = BN * TILE_F * 4;

        constexpr int NIT = HID / BKT;
        load_tile(0, 0);
        cp_commit();
        for (int it = 0; it < NIT; ++it) {
            if (it + 1 < NIT) load_tile((it + 1) & 1, (it + 1) * BKT);
            cp_commit();
            cp_wait1();
            __syncthreads();
            int buf = it & 1;
            uint32_t aoff = buf * bufAoff, boff = buf * bufBoff;
#pragma unroll
            for (int ks = 0; ks < BKT; ks += 8) {
                unsigned a[4][4], b[2][4];
#pragma unroll
                for (int mi = 0; mi < 4; mi++)
                    ldsm4(a[mi][0], a[mi][1], a[mi][2], a[mi][3], aaddr[mi] + aoff + ks * 4);
#pragma unroll
                for (int p = 0; p < 2; p++)
                    ldsm4(b[p][0], b[p][1], b[p][2], b[p][3], baddr[p] + boff + ks * 4);
#pragma unroll
                for (int mi = 0; mi < 4; mi++)
#pragma unroll
                    for (int ni = 0; ni < 4; ni++)
                        mma_tf32(acc[mi][ni], a[mi], &b[ni >> 1][(ni & 1) * 2]);
            }
            __syncthreads();
        }
    }

    // ---- fused LSTM cell epilogue (gate-permuted columns n'=4*hid+gate) ------
#pragma unroll
    for (int mi = 0; mi < 4; mi++) {
#pragma unroll
        for (int ni = 0; ni < 4; ni++) {
            float* a4 = acc[mi][ni];
            float s0 = __shfl_xor_sync(0xffffffffu, a4[0], 1);
            float s1 = __shfl_xor_sync(0xffffffffu, a4[1], 1);
            float s2 = __shfl_xor_sync(0xffffffffu, a4[2], 1);
            float s3 = __shfl_xor_sync(0xffffffffu, a4[3], 1);
            int odd = tg & 1;
            int j = ((n0 + wn + 8 * ni) >> 2) + (tg >> 1);   // hidden index 0..255
            int b = m0 + wm + 16 * mi + g + (odd ? 8 : 0);
            float gi, gf, gg, go;
            if (!odd) { gi = a4[0]; gf = a4[1]; gg = s0;    go = s1;    }
            else      { gi = s2;    gf = s3;    gg = a4[2]; go = a4[3]; }
            float4 xv = *(const float4*)&xg[(size_t)b * G4 + 4 * j];
            gi += xv.x; gf += xv.y; gg += xv.z; go += xv.w;
            float cp = (s > 0) ? cs[(size_t)b * HID + j] : 0.0f;
            float ii = 1.0f / (1.0f + expf(-gi));
            float ff = 1.0f / (1.0f + expf(-gf));
            float gt = tanhf(gg);
            float oo = 1.0f / (1.0f + expf(-go));
            float c = ff * cp + ii * gt;
            cs[(size_t)b * HID + j] = c;
            hout[(size_t)b * (2 * HID) + j] = f2tf32f(oo * tanhf(c));
        }
    }
}

// ---------------- launcher ---------------------------------------------------
extern "C" void kernel_launch(void* const* d_in, const int* in_sizes, int n_in,
                              void* d_out, int out_size) {
    const int*   words   = (const int*)d_in[0];
    const int*   lengths = (const int*)d_in[1];
    const float* emb     = (const float*)d_in[2];
    const float* enc_w   = (const float*)d_in[3];
    const float* enc_b   = (const float*)d_in[4];
    const float* wih_f   = (const float*)d_in[5];
    const float* whh_f   = (const float*)d_in[6];
    const float* bih_f   = (const float*)d_in[7];
    const float* bhh_f   = (const float*)d_in[8];
    const float* wih_b   = (const float*)d_in[9];
    const float* whh_b   = (const float*)d_in[10];
    const float* bih_b   = (const float*)d_in[11];
    const float* bhh_b   = (const float*)d_in[12];
    const float* out_w   = (const float*)d_in[13];
    const float* out_b   = (const float*)d_in[14];
    float* out = (float*)d_out;

    const int M = TT * NB;  // 81920

    prep_enc<<<CVEC, 256>>>(enc_w);
    prep_ih<<<dim3(G4, 2), 256>>>(wih_f, wih_b, bih_f, bhh_f, bih_b, bhh_b);
    prep_hh<<<dim3(G4, 2), 256>>>(whh_f, whh_b);
    prep_out<<<OUTD, 256>>>(out_w);

    interp_kernel<<<NB, 256>>>(words, lengths, emb);

    gemm_tc<0><<<dim3(CVEC / BN, M / BM), 256>>>(enc_b, (float*)0, 0);
    gemm_tc<1><<<dim3(G4 / BN, M / BM), 256>>>((const float*)0, (float*)0, 0);
    gemm_tc<1><<<dim3(G4 / BN, M / BM), 256>>>((const float*)0, (float*)0, 1);

    for (int s = 0; s < TT; s++) {
        lstm_step_mma<<<dim3(G4 / BN, NB / BM, 2), 256>>>(s);
    }

    gemm_tc<2><<<dim3(OUTD / BN, M / BM), 256>>>(out_b, out, 0);
}